// round 17
// baseline (speedup 1.0000x reference)
#include <cuda_runtime.h>
#include <cuda_fp16.h>
#include <cstdint>

// Problem constants
#define B_ 16
#define K_ 49
#define T_ 256
#define H_ 512
#define D_ 512

// Output packing: (c_hat_t, alpha_t, beta_t) flattened in order
#define OUT_ALPHA (B_ * T_ * H_)              // 2097152
#define OUT_BETA  (OUT_ALPHA + B_ * T_ * K_)  // 2297856

// Scratch: cv and cs stored as fp16 (packed pairs) -> TANH.H2 + half the LDG
// bytes in the fused z-loop. cg stays f32.
__device__ __half g_cv[B_ * K_ * D_];   // half(V @ Wv + bv)
__device__ float  g_cg[B_ * T_ * D_];   // h_t @ Wg + bg
__device__ __half g_cs[B_ * T_ * D_];   // half(s_t @ Ws + bs)

// pack two f32 -> f16x2
__device__ __forceinline__ uint32_t pack_h2(float lo, float hi)
{ uint32_t d; asm("cvt.rn.f16x2.f32 %0, %1, %2;" : "=r"(d) : "f"(hi), "f"(lo)); return d; }

__device__ __forceinline__ uint32_t hadd2(uint32_t a, uint32_t b)
{ uint32_t d; asm("add.rn.f16x2 %0, %1, %2;" : "=r"(d) : "r"(a), "r"(b)); return d; }

__device__ __forceinline__ uint32_t tanh_h2(uint32_t a)
{ uint32_t d; asm("tanh.approx.f16x2 %0, %1;" : "=r"(d) : "r"(a)); return d; }

__device__ __forceinline__ float2 h2_to_f2(uint32_t t)
{
    float f0, f1;
    asm("{\n\t.reg .f16 l, h;\n\tmov.b32 {l, h}, %2;\n\t"
        "cvt.f32.f16 %0, l;\n\tcvt.f32.f16 %1, h;\n\t}"
        : "=f"(f0), "=f"(f1) : "r"(t));
    return make_float2(f0, f1);
}

__device__ __forceinline__ void cpa16(uint32_t dst, const void* src, int sz)
{
    asm volatile("cp.async.cg.shared.global [%0], [%1], 16, %2;"
                 :: "r"(dst), "l"(src), "r"(sz) : "memory");
}
__device__ __forceinline__ void cpa_commit()
{ asm volatile("cp.async.commit_group;" ::: "memory"); }
__device__ __forceinline__ void cpa_wait0()
{ asm volatile("cp.async.wait_group 0;" ::: "memory"); }

// ---------------------------------------------------------------------------
// Merged TF32 mma.sync GEMM: all three C[M,512] = A[M,512]@W + bias.
// K-tile 16, double-buffered smem, cp.async, ONE sync per tile.
// As stride 28 (conflict-free frag reads), Bs stride 132.
// cv/cs epilogues store packed fp16 pairs; cg stores f32.
// ---------------------------------------------------------------------------
#define AS_STRIDE 28
#define BS_STRIDE 132

__global__ __launch_bounds__(256)
void gemm3_tf32_kernel(const float* __restrict__ V, const float* __restrict__ h_t,
                       const float* __restrict__ s_t,
                       const float* __restrict__ Wv, const float* __restrict__ bv,
                       const float* __restrict__ Wg, const float* __restrict__ bg,
                       const float* __restrict__ Wss, const float* __restrict__ bss)
{
    __shared__ float As[2][128 * AS_STRIDE];
    __shared__ float Bs[2][16 * BS_STRIDE];

    const int nt = blockIdx.x;         // 0..3
    int mt = blockIdx.y;               // 0..70
    const float *A, *W, *bias;
    float* Cf = nullptr;
    __half* Ch = nullptr;
    int M;
    if (mt < 7)       { A = V;   W = Wv;  bias = bv;  Ch = g_cv; M = B_ * K_; }
    else if (mt < 39) { A = h_t; W = Wg;  bias = bg;  Cf = g_cg; M = B_ * T_; mt -= 7; }
    else              { A = s_t; W = Wss; bias = bss; Ch = g_cs; M = B_ * T_; mt -= 39; }

    const int tid  = threadIdx.x;
    const int lane = tid & 31;
    const int wid  = tid >> 5;
    const int g    = lane >> 2;
    const int tg   = lane & 3;
    const int warp_m = (wid >> 2) * 64;
    const int warp_n = (wid & 3) * 32;

    const int mbase = mt * 128;
    const int nbase = nt * 128;

    float acc[4][4][4];
    #pragma unroll
    for (int i = 0; i < 4; i++)
        #pragma unroll
        for (int j = 0; j < 4; j++)
            #pragma unroll
            for (int q = 0; q < 4; q++) acc[i][j][q] = 0.f;

    // load mappings (per thread, per tile: 2 A + 2 B cp.asyncs of 16B)
    const int a_m0 = tid >> 2;          // +i*64 -> m within tile
    const int a_k4 = (tid & 3) * 4;     // k within tile
    const int w_k0 = tid >> 5;          // +i*8 -> k within tile
    const int w_n4 = (tid & 31) * 4;

    uint32_t as_base = (uint32_t)__cvta_generic_to_shared(&As[0][0]);
    uint32_t bs_base = (uint32_t)__cvta_generic_to_shared(&Bs[0][0]);
    const uint32_t as_sz = 128 * AS_STRIDE * 4;
    const uint32_t bs_sz = 16 * BS_STRIDE * 4;

    // issue tile kt (elements [kt, kt+16)) into buffer s
    auto issue = [&](int kt, int s) {
        #pragma unroll
        for (int i = 0; i < 2; i++) {
            const int m = a_m0 + i * 64;
            const int row = mbase + m;
            cpa16(as_base + s * as_sz + (m * AS_STRIDE + a_k4) * 4,
                  &A[(size_t)row * 512 + kt + a_k4], (row < M) ? 16 : 0);
        }
        #pragma unroll
        for (int i = 0; i < 2; i++) {
            const int k = w_k0 + i * 8;
            cpa16(bs_base + s * bs_sz + (k * BS_STRIDE + w_n4) * 4,
                  &W[(size_t)(kt + k) * 512 + nbase + w_n4], 16);
        }
    };

    issue(0, 0);
    cpa_commit();

    for (int it = 0; it < 32; it++) {
        cpa_wait0();
        __syncthreads();
        if (it + 1 < 32) {
            issue((it + 1) * 16, (it + 1) & 1);
            cpa_commit();
        }
        const float* __restrict__ as = As[it & 1];
        const float* __restrict__ bs = Bs[it & 1];

        #pragma unroll
        for (int kb = 0; kb < 16; kb += 8) {
            uint32_t af[4][4], bf[4][2];
            #pragma unroll
            for (int mi = 0; mi < 4; mi++) {
                const int m0 = warp_m + mi * 16;
                af[mi][0] = __float_as_uint(as[(m0 + g)     * AS_STRIDE + kb + tg]);
                af[mi][1] = __float_as_uint(as[(m0 + g + 8) * AS_STRIDE + kb + tg]);
                af[mi][2] = __float_as_uint(as[(m0 + g)     * AS_STRIDE + kb + tg + 4]);
                af[mi][3] = __float_as_uint(as[(m0 + g + 8) * AS_STRIDE + kb + tg + 4]);
            }
            #pragma unroll
            for (int ni = 0; ni < 4; ni++) {
                const int n_ = warp_n + ni * 8 + g;
                bf[ni][0] = __float_as_uint(bs[(kb + tg)     * BS_STRIDE + n_]);
                bf[ni][1] = __float_as_uint(bs[(kb + tg + 4) * BS_STRIDE + n_]);
            }
            #pragma unroll
            for (int mi = 0; mi < 4; mi++)
                #pragma unroll
                for (int ni = 0; ni < 4; ni++) {
                    asm volatile(
                        "mma.sync.aligned.m16n8k8.row.col.f32.tf32.tf32.f32 "
                        "{%0,%1,%2,%3}, {%4,%5,%6,%7}, {%8,%9}, {%0,%1,%2,%3};"
                        : "+f"(acc[mi][ni][0]), "+f"(acc[mi][ni][1]),
                          "+f"(acc[mi][ni][2]), "+f"(acc[mi][ni][3])
                        : "r"(af[mi][0]), "r"(af[mi][1]), "r"(af[mi][2]), "r"(af[mi][3]),
                          "r"(bf[ni][0]), "r"(bf[ni][1]));
                }
        }
        __syncthreads();   // mma done before next iter's cp.async may overwrite
    }

    // Epilogue: bias, then store (f32 for cg; packed fp16 pairs for cv/cs).
    #pragma unroll
    for (int mi = 0; mi < 4; mi++) {
        const int r0 = mbase + warp_m + mi * 16 + g;
        const int r1 = r0 + 8;
        #pragma unroll
        for (int ni = 0; ni < 4; ni++) {
            const int c = nbase + warp_n + ni * 8 + tg * 2;
            const float2 bv2 = *reinterpret_cast<const float2*>(&bias[c]);
            const float o00 = acc[mi][ni][0] + bv2.x, o01 = acc[mi][ni][1] + bv2.y;
            const float o10 = acc[mi][ni][2] + bv2.x, o11 = acc[mi][ni][3] + bv2.y;
            if (Cf) {
                if (r0 < M)
                    *reinterpret_cast<float2*>(&Cf[(size_t)r0 * 512 + c]) = make_float2(o00, o01);
                if (r1 < M)
                    *reinterpret_cast<float2*>(&Cf[(size_t)r1 * 512 + c]) = make_float2(o10, o11);
            } else {
                if (r0 < M)
                    *reinterpret_cast<uint32_t*>(&Ch[(size_t)r0 * 512 + c]) = pack_h2(o00, o01);
                if (r1 < M)
                    *reinterpret_cast<uint32_t*>(&Ch[(size_t)r1 * 512 + c]) = pack_h2(o10, o11);
            }
        }
    }
}

// z-row lane partial over d = 256j + 8*lane + c (c=0..7), fp16x2 pipeline.
__device__ __forceinline__ float z_row_h2(const __half* __restrict__ r,
                                          const uint32_t cgh[8], const float whr[16])
{
    float acc = 0.f;
    #pragma unroll
    for (int j = 0; j < 2; j++) {
        const uint4 v = *reinterpret_cast<const uint4*>(r + j * 256);
        uint32_t t0 = tanh_h2(hadd2(v.x, cgh[4 * j + 0]));
        uint32_t t1 = tanh_h2(hadd2(v.y, cgh[4 * j + 1]));
        uint32_t t2 = tanh_h2(hadd2(v.z, cgh[4 * j + 2]));
        uint32_t t3 = tanh_h2(hadd2(v.w, cgh[4 * j + 3]));
        float2 f0 = h2_to_f2(t0);
        float2 f1 = h2_to_f2(t1);
        float2 f2 = h2_to_f2(t2);
        float2 f3 = h2_to_f2(t3);
        acc = fmaf(f0.x, whr[8 * j + 0], acc);
        acc = fmaf(f0.y, whr[8 * j + 1], acc);
        acc = fmaf(f1.x, whr[8 * j + 2], acc);
        acc = fmaf(f1.y, whr[8 * j + 3], acc);
        acc = fmaf(f2.x, whr[8 * j + 4], acc);
        acc = fmaf(f2.y, whr[8 * j + 5], acc);
        acc = fmaf(f3.x, whr[8 * j + 6], acc);
        acc = fmaf(f3.y, whr[8 * j + 7], acc);
    }
    return acc;
}

// ---------------------------------------------------------------------------
// Fused z + softmax kernel: one CTA per (b,t), 128 threads (4 warps).
// ---------------------------------------------------------------------------
__global__ __launch_bounds__(128, 8)
void fused_z_kernel(const float* __restrict__ Wh, const float* __restrict__ bh,
                    float* __restrict__ out)
{
    __shared__ float z_s[52];

    const int tid  = threadIdx.x;
    const int lane = tid & 31;
    const int w    = tid >> 5;
    const int bt = blockIdx.x;
    const int b  = bt >> 8;

    uint32_t cgh[8];
    float whr[16];
    {
        const float* __restrict__ cgrow = g_cg + (size_t)bt * 512 + lane * 8;
        const float* __restrict__ whrow = Wh + lane * 8;
        #pragma unroll
        for (int j = 0; j < 2; j++) {
            float4 a0 = *reinterpret_cast<const float4*>(&cgrow[j * 256]);
            float4 a1 = *reinterpret_cast<const float4*>(&cgrow[j * 256 + 4]);
            cgh[4 * j + 0] = pack_h2(a0.x, a0.y);
            cgh[4 * j + 1] = pack_h2(a0.z, a0.w);
            cgh[4 * j + 2] = pack_h2(a1.x, a1.y);
            cgh[4 * j + 3] = pack_h2(a1.z, a1.w);
            float4 w0 = *reinterpret_cast<const float4*>(&whrow[j * 256]);
            float4 w1 = *reinterpret_cast<const float4*>(&whrow[j * 256 + 4]);
            whr[8 * j + 0] = w0.x; whr[8 * j + 1] = w0.y;
            whr[8 * j + 2] = w0.z; whr[8 * j + 3] = w0.w;
            whr[8 * j + 4] = w1.x; whr[8 * j + 5] = w1.y;
            whr[8 * j + 6] = w1.z; whr[8 * j + 7] = w1.w;
        }
    }
    const float bhv = bh[0];

    const __half* __restrict__ cvb = g_cv + (size_t)b * (K_ * 512) + lane * 8;

    const int n = (K_ - w + 3) >> 2;   // 13,12,12,12
    int i = 0;
    for (; i + 1 < n; i += 2) {
        const int k0 = w + 4 * i;
        const int k1 = k0 + 4;
        float a0 = z_row_h2(cvb + (size_t)k0 * 512, cgh, whr);
        float a1 = z_row_h2(cvb + (size_t)k1 * 512, cgh, whr);
        #pragma unroll
        for (int o = 16; o > 0; o >>= 1) {
            a0 += __shfl_xor_sync(0xffffffffu, a0, o);
            a1 += __shfl_xor_sync(0xffffffffu, a1, o);
        }
        if (lane == 0) { z_s[k0] = a0 + bhv; z_s[k1] = a1 + bhv; }
    }
    if (i < n) {
        const int k0 = w + 4 * i;
        float a0 = z_row_h2(cvb + (size_t)k0 * 512, cgh, whr);
        #pragma unroll
        for (int o = 16; o > 0; o >>= 1)
            a0 += __shfl_xor_sync(0xffffffffu, a0, o);
        if (lane == 0) z_s[k0] = a0 + bhv;
    }

    if (w == 3) {
        float acc = z_row_h2(g_cs + (size_t)bt * 512 + lane * 8, cgh, whr);
        #pragma unroll
        for (int o = 16; o > 0; o >>= 1)
            acc += __shfl_xor_sync(0xffffffffu, acc, o);
        if (lane == 0) z_s[K_] = acc + bhv;
    }
    __syncthreads();

    if (w == 0) {
        float z0 = (lane < K_)      ? z_s[lane]      : -1e30f;
        float z1 = (lane + 32 < K_) ? z_s[lane + 32] : -1e30f;
        float ze = z_s[K_];
        float m = fmaxf(fmaxf(z0, z1), ze);
        #pragma unroll
        for (int o = 16; o > 0; o >>= 1)
            m = fmaxf(m, __shfl_xor_sync(0xffffffffu, m, o));

        float e0 = (lane < K_)      ? __expf(z0 - m) : 0.f;
        float e1 = (lane + 32 < K_) ? __expf(z1 - m) : 0.f;
        float ee = __expf(ze - m);

        float s = e0 + e1;
        #pragma unroll
        for (int o = 16; o > 0; o >>= 1)
            s += __shfl_xor_sync(0xffffffffu, s, o);
        const float beta = ee / (s + ee);
        const float inv = 1.0f / s;

        if (lane < K_)
            out[OUT_ALPHA + (size_t)bt * K_ + lane] = e0 * inv;
        if (lane + 32 < K_)
            out[OUT_ALPHA + (size_t)bt * K_ + lane + 32] = e1 * inv;
        if (lane == 0)
            out[OUT_BETA + bt] = beta;
    }
}

// ---------------------------------------------------------------------------
// c_t in SIMT fp32 (full precision): tile 64 t-rows x 128 h-cols per CTA,
// 128 threads, each thread 8 rows x (4+4) cols. alpha/V staged in smem.
// c_hat = c + beta*(s - c) in the epilogue. Grid (4 h-tiles, 64 t-tiles).
// ---------------------------------------------------------------------------
__global__ __launch_bounds__(128)
void ct_simt_kernel(const float* __restrict__ V, const float* __restrict__ s_t,
                    float* __restrict__ out)
{
    __shared__ float al_s[64 * 52];     // alpha [m][k] stride 52
    __shared__ float v_s[K_ * 136];     // V [k][n] stride 136
    __shared__ float beta_s2[64];

    const int tid = threadIdx.x;
    const int nb  = blockIdx.x * 128;       // h-col base
    const int tb  = blockIdx.y * 64;        // global bt base
    const int b   = tb >> 8;

    // stage alpha [64 x 49]
    {
        const float* __restrict__ arow = out + OUT_ALPHA + (size_t)tb * K_;
        for (int idx = tid; idx < 64 * K_; idx += 128) {
            const int m = idx / K_;
            const int k = idx - m * K_;
            al_s[m * 52 + k] = arow[idx];
        }
    }
    // stage V [49 x 128]
    {
        const float* __restrict__ vb = V + (size_t)b * (K_ * 512) + nb;
        for (int idx = tid; idx < K_ * 32; idx += 128) {
            const int k  = idx >> 5;
            const int c4 = (idx & 31) * 4;
            *reinterpret_cast<float4*>(&v_s[k * 136 + c4]) =
                *reinterpret_cast<const float4*>(&vb[(size_t)k * 512 + c4]);
        }
    }
    if (tid < 64) beta_s2[tid] = out[OUT_BETA + tb + tid];
    __syncthreads();

    const int tx = tid & 15;   // col group: cols tx*4..+3 and 64+tx*4..+3
    const int ty = tid >> 4;   // row group: rows ty*8..+7

    float acc[8][8];
    #pragma unroll
    for (int r = 0; r < 8; r++)
        #pragma unroll
        for (int c = 0; c < 8; c++) acc[r][c] = 0.f;

    for (int k = 0; k < K_; k++) {
        const float4 v0 = *reinterpret_cast<const float4*>(&v_s[k * 136 + tx * 4]);
        const float4 v1 = *reinterpret_cast<const float4*>(&v_s[k * 136 + 64 + tx * 4]);
        #pragma unroll
        for (int r = 0; r < 8; r++) {
            const float a = al_s[(ty * 8 + r) * 52 + k];
            acc[r][0] = fmaf(a, v0.x, acc[r][0]);
            acc[r][1] = fmaf(a, v0.y, acc[r][1]);
            acc[r][2] = fmaf(a, v0.z, acc[r][2]);
            acc[r][3] = fmaf(a, v0.w, acc[r][3]);
            acc[r][4] = fmaf(a, v1.x, acc[r][4]);
            acc[r][5] = fmaf(a, v1.y, acc[r][5]);
            acc[r][6] = fmaf(a, v1.z, acc[r][6]);
            acc[r][7] = fmaf(a, v1.w, acc[r][7]);
        }
    }

    // epilogue: blend + store
    #pragma unroll
    for (int r = 0; r < 8; r++) {
        const int m  = ty * 8 + r;
        const int bt = tb + m;
        const float beta = beta_s2[m];
        const size_t o0 = (size_t)bt * 512 + nb + tx * 4;
        {
            const float4 sv = *reinterpret_cast<const float4*>(&s_t[o0]);
            float4 o;
            o.x = fmaf(beta, sv.x - acc[r][0], acc[r][0]);
            o.y = fmaf(beta, sv.y - acc[r][1], acc[r][1]);
            o.z = fmaf(beta, sv.z - acc[r][2], acc[r][2]);
            o.w = fmaf(beta, sv.w - acc[r][3], acc[r][3]);
            *reinterpret_cast<float4*>(&out[o0]) = o;
        }
        {
            const float4 sv = *reinterpret_cast<const float4*>(&s_t[o0 + 64]);
            float4 o;
            o.x = fmaf(beta, sv.x - acc[r][4], acc[r][4]);
            o.y = fmaf(beta, sv.y - acc[r][5], acc[r][5]);
            o.z = fmaf(beta, sv.z - acc[r][6], acc[r][6]);
            o.w = fmaf(beta, sv.w - acc[r][7], acc[r][7]);
            *reinterpret_cast<float4*>(&out[o0 + 64]) = o;
        }
    }
}

// ---------------------------------------------------------------------------
extern "C" void kernel_launch(void* const* d_in, const int* in_sizes, int n_in,
                              void* d_out, int out_size)
{
    (void)in_sizes; (void)n_in; (void)out_size;
    const float* V   = (const float*)d_in[0];
    const float* h_t = (const float*)d_in[1];
    const float* s_t = (const float*)d_in[2];
    const float* Wv  = (const float*)d_in[3];
    const float* bv  = (const float*)d_in[4];
    const float* Wg  = (const float*)d_in[5];
    const float* bg  = (const float*)d_in[6];
    const float* Ws  = (const float*)d_in[7];
    const float* bs  = (const float*)d_in[8];
    const float* Wh  = (const float*)d_in[9];
    const float* bh  = (const float*)d_in[10];
    float* out = (float*)d_out;

    gemm3_tf32_kernel<<<dim3(4, 71), 256>>>(V, h_t, s_t, Wv, bv, Wg, bg, Ws, bs);
    fused_z_kernel<<<dim3(B_ * T_), 128>>>(Wh, bh, out);
    ct_simt_kernel<<<dim3(4, 64), 128>>>(V, s_t, out);
}